// round 9
// baseline (speedup 1.0000x reference)
#include <cuda_runtime.h>
#include <cstdint>

// CBModel: output = concat(gen_poses [2,32,18,256,256], step_poses [2,32,18,256,256]) fp32
//   = 604 MB of zeros + <=2304 one-hot 1.0s.
//
// Single-kernel design (no node boundaries): 144 blocks, each owning 16 planes
// (4 MB contiguous). Each block zeroes a 32 KB SMEM buffer once, then one
// elected thread streams 128 x 32KB cp.async.bulk S2G (TMA) stores of zeros.
// After wait_group 0, threads 0..15 write the block's hot 1.0s inline.
// Rationale: TMA bulk stores bypass the SM store pipeline (like the driver
// memset path, 7.37 TB/s) while leaving SMs idle -> clock/power headroom for
// the memory subsystem. Eliminates the ~4.5us trailing-kernel floor entirely.

static constexpr int BC      = 32 * 18;    // 576
static constexpr int C_KP    = 18;
static constexpr int HW      = 256 * 256;  // 65536 floats per plane
static constexpr int PLANES  = 4 * BC;     // 2304

static constexpr int PLANES_PER_BLOCK = 16;
static constexpr int GRID             = PLANES / PLANES_PER_BLOCK;  // 144
static constexpr int SMEM_BYTES       = 32768;                     // 32 KB chunk
static constexpr size_t BLOCK_BYTES   = (size_t)PLANES_PER_BLOCK * HW * 4; // 4 MB
static constexpr int CHUNKS           = (int)(BLOCK_BYTES / SMEM_BYTES);   // 128

// Hot index for a plane: -1 if out of bounds, else x*256+y.
// Bit-exact to the reference: jnp.trunc+int32 == C trunc cast; floor_divide via
// floorf((b-a)/3); step coords accumulated sequentially (two float roundings).
__device__ __forceinline__ int plane_hot(int plane,
                                         const float* __restrict__ pose1,
                                         const float* __restrict__ pose2)
{
    float cx, cy;
    if (plane < 2 * BC) {
        // gen half: sample-0 coords, replicated over batch
        const int k   = plane / BC;            // 0 -> pose1, 1 -> pose2
        const int rem = plane - k * BC;
        const int c   = rem % C_KP;
        const float* P = k ? pose2 : pose1;
        cx = P[2 * c];
        cy = P[2 * c + 1];
    } else {
        const int q   = plane - 2 * BC;
        const int s   = q / BC;                // 0 -> one step, 1 -> two steps
        const int rem = q - s * BC;            // rem = b*18 + c
        const float ax = pose1[2 * rem],  ay = pose1[2 * rem + 1];
        const float bx = pose2[2 * rem],  by = pose2[2 * rem + 1];
        const float sx = floorf((bx - ax) / 3.0f);
        const float sy = floorf((by - ay) / 3.0f);
        cx = ax + sx;  cy = ay + sy;
        if (s == 1) { cx += sx; cy += sy; }
    }
    const int x = (int)cx;
    const int y = (int)cy;
    const bool valid = (x >= 0) & (x <= 255) & (y >= 0) & (y <= 255);
    return valid ? ((x << 8) | y) : -1;
}

__device__ __forceinline__ uint32_t smem_addr_u32(const void* p)
{
    uint32_t a;
    asm("{ .reg .u64 t; cvta.to.shared.u64 t, %1; cvt.u32.u64 %0, t; }"
        : "=r"(a) : "l"(p));
    return a;
}

__global__ __launch_bounds__(256, 1)
void cbmodel_tma_fill_kernel(const float* __restrict__ pose1,
                             const float* __restrict__ pose2,
                             float* __restrict__ out)
{
    __shared__ __align__(128) float zbuf[SMEM_BYTES / 4];

    const int tid = threadIdx.x;
    const int b   = blockIdx.x;

    // Zero the SMEM source buffer (2048 float4 / 256 threads = 8 each).
    float4* z4 = reinterpret_cast<float4*>(zbuf);
    const float4 z = make_float4(0.0f, 0.0f, 0.0f, 0.0f);
    #pragma unroll
    for (int i = tid; i < SMEM_BYTES / 16; i += 256) {
        z4[i] = z;
    }

    // Threads 0..15 precompute their plane's hot index while SMEM is zeroed.
    int my_plane = -1, my_hot = -1;
    if (tid < PLANES_PER_BLOCK) {
        my_plane = b * PLANES_PER_BLOCK + tid;
        my_hot   = plane_hot(my_plane, pose1, pose2);
    }

    __syncthreads();
    // Order generic-proxy SMEM writes before async-proxy (TMA) reads.
    asm volatile("fence.proxy.async.shared::cta;" ::: "memory");

    if (tid == 0) {
        const uint32_t src = smem_addr_u32(zbuf);
        char* gbase = reinterpret_cast<char*>(out) + (size_t)b * BLOCK_BYTES;
        #pragma unroll 4
        for (int c = 0; c < CHUNKS; ++c) {
            asm volatile(
                "cp.async.bulk.global.shared::cta.bulk_group [%0], [%1], %2;"
                :: "l"(gbase + (size_t)c * SMEM_BYTES), "r"(src), "r"(SMEM_BYTES)
                : "memory");
        }
        asm volatile("cp.async.bulk.commit_group;" ::: "memory");
        asm volatile("cp.async.bulk.wait_group 0;" ::: "memory");
    }

    // All TMA stores for this block's slice are complete and visible.
    __syncthreads();

    // Inline hot writes: each of threads 0..15 stores its plane's single 1.0.
    if (tid < PLANES_PER_BLOCK && my_hot >= 0) {
        out[(size_t)my_plane * HW + my_hot] = 1.0f;
    }
}

extern "C" void kernel_launch(void* const* d_in, const int* in_sizes, int n_in,
                              void* d_out, int out_size)
{
    const float* pose1 = (const float*)d_in[0];   // [32,18,2] float32
    const float* pose2 = (const float*)d_in[1];   // [32,18,2] float32
    float* out = (float*)d_out;

    (void)in_sizes; (void)n_in; (void)out_size;

    cbmodel_tma_fill_kernel<<<GRID, 256>>>(pose1, pose2, out);
}